// round 11
// baseline (speedup 1.0000x reference)
#include <cuda_runtime.h>
#include <cuda_fp16.h>
#include <math.h>

#define BB 32
#define TT 64
#define NT 2048        // BB*TT images
#define KSPLIT 16

// Scratch (static device globals — allocation-free kernel_launch)
__device__ __half g_feats[(size_t)NT * 16384];        // conv2 out fp16: [n][oc*256+p]
__device__ float  g_prep[(size_t)KSPLIT * NT * 128];  // split-K partials (fp32)
__device__ uint4  g_w1f[192];                          // conv1 B-fragments (3 ks x 2 ntp x 32)
__device__ uint4  g_w2f[4096];                         // conv2 B-fragments (32 ks x 4 ntp x 32)
__device__ uint4  g_bwf[262144];                       // bb_w B-fragments (1024 ks x 8 ntp x 32)

// ---------------------------------------------------------------------------
// helpers
// ---------------------------------------------------------------------------
__device__ __forceinline__ unsigned h2pack(float lo, float hi) {
    __half2 h = __floats2half2_rn(lo, hi);
    return *(unsigned*)&h;
}

#define MMA_F16(d, a0, a1, a2, a3, b0, b1)                                    \
    asm volatile("mma.sync.aligned.m16n8k16.row.col.f32.f16.f16.f32 "         \
                 "{%0,%1,%2,%3}, {%4,%5,%6,%7}, {%8,%9}, {%0,%1,%2,%3};"      \
                 : "+f"(d[0]), "+f"(d[1]), "+f"(d[2]), "+f"(d[3])             \
                 : "r"(a0), "r"(a1), "r"(a2), "r"(a3), "r"(b0), "r"(b1))

__device__ __forceinline__ float fast_tanh(float x) {
    float e = __expf(2.f * x);
    return 1.f - __fdividef(2.f, e + 1.f);
}
__device__ __forceinline__ float fast_sig(float x) {
    return __fdividef(1.f, 1.f + __expf(-x));
}

// ---------------------------------------------------------------------------
// prep: pack all B operands into m16n8k16 fragment layout (fp16)
// blocks 0..1023: bbw kstep tiles. blocks 1024..1039: w2 (spread, no straggler).
// block 1040: w1.
// ---------------------------------------------------------------------------
__global__ void prep_kernel(const float* __restrict__ w1, const float* __restrict__ w2,
                            const float* __restrict__ bbw) {
    const int blk = blockIdx.x, t = threadIdx.x;
    if (blk < 1024) {
        __shared__ float sm[2048];            // 16 k-rows x 128 n
        const float4* src = (const float4*)(bbw + (size_t)blk * 16 * 128);
        for (int i = t; i < 512; i += 256) ((float4*)sm)[i] = src[i];
        __syncthreads();
        int ntp = t >> 5, lane = t & 31;
        int tig = lane & 3, gid = lane >> 2;
        int c = tig * 2, n = ntp * 16 + gid;
        uint4 v;
        v.x = h2pack(sm[c * 128 + n],           sm[(c + 1) * 128 + n]);
        v.y = h2pack(sm[(c + 8) * 128 + n],     sm[(c + 9) * 128 + n]);
        v.z = h2pack(sm[c * 128 + n + 8],       sm[(c + 1) * 128 + n + 8]);
        v.w = h2pack(sm[(c + 8) * 128 + n + 8], sm[(c + 9) * 128 + n + 8]);
        g_bwf[blk * 256 + t] = v;
    } else if (blk < 1040) {
        int idx = (blk - 1024) * 256 + t;     // 4096 total, 16 blocks
        int ks = idx >> 7, ntp = (idx >> 5) & 3, lane = idx & 31;
        int tig = lane & 3, gid = lane >> 2;
        int c = ks * 16 + tig * 2, n = ntp * 16 + gid;
        uint4 v;
        v.x = h2pack(w2[n * 512 + c],           w2[n * 512 + c + 1]);
        v.y = h2pack(w2[n * 512 + c + 8],       w2[n * 512 + c + 9]);
        v.z = h2pack(w2[(n + 8) * 512 + c],     w2[(n + 8) * 512 + c + 1]);
        v.w = h2pack(w2[(n + 8) * 512 + c + 8], w2[(n + 8) * 512 + c + 9]);
        g_w2f[idx] = v;
    } else {
        if (t < 192) {
            int ks = t >> 6, ntp = (t >> 5) & 1, lane = t & 31;
            int tig = lane & 3, gid = lane >> 2;
            int c = ks * 16 + tig * 2, n = ntp * 16 + gid;
            uint4 v;
            v.x = h2pack(w1[n * 48 + c],           w1[n * 48 + c + 1]);
            v.y = h2pack(w1[n * 48 + c + 8],       w1[n * 48 + c + 9]);
            v.z = h2pack(w1[(n + 8) * 48 + c],     w1[(n + 8) * 48 + c + 1]);
            v.w = h2pack(w1[(n + 8) * 48 + c + 8], w1[(n + 8) * 48 + c + 9]);
            g_w1f[t] = v;
        }
    }
}

// ---------------------------------------------------------------------------
// Fused conv1+conv2 per image, fp16 m16n8k16. One CTA per image, 512 threads.
// Occupancy 2: w2 B-fragments are read straight from gmem (L1/L2-resident).
// ---------------------------------------------------------------------------
#define CB_ACT 0
#define CB_X   73984
#define CB_W1  100128
#define CB_P2  103200
#define CB_P1  105248
#define CB_BI1 105440
#define CB_BI2 105568
#define CB_TOT 105824

__global__ __launch_bounds__(512, 2) void fused_conv_kernel(
    const float* __restrict__ x_vis,
    const float* __restrict__ b1g, const float* __restrict__ b2g) {
    extern __shared__ char smc[];
    __half* act_s = (__half*)(smc + CB_ACT);
    __half* xs    = (__half*)(smc + CB_X);
    uint4*  w1f   = (uint4*)(smc + CB_W1);
    int*    p2t   = (int*)(smc + CB_P2);
    int*    p1t   = (int*)(smc + CB_P1);
    float*  bi1   = (float*)(smc + CB_BI1);
    float*  bi2   = (float*)(smc + CB_BI2);

    const int n = blockIdx.x, tid = threadIdx.x;
    const int lane = tid & 31, w = tid >> 5;
    const int tig = lane & 3, gid = lane >> 2;

    // zero act + x regions (6258 uint4)
    {
        uint4 z = make_uint4(0, 0, 0, 0);
        uint4* zp = (uint4*)smc;
        for (int t = tid; t < 6258; t += 512) zp[t] = z;
    }
    if (tid < 48)  p1t[tid] = (tid >> 4) * 4356 + ((tid >> 2) & 3) * 66 + (tid & 3);
    if (tid < 512) p2t[tid] = (tid >> 4) * 1156 + ((tid >> 2) & 3) * 34 + (tid & 3);
    if (tid < 192) w1f[tid] = g_w1f[tid];
    if (tid < 32) bi1[tid] = b1g[tid];
    if (tid < 64) bi2[tid] = b2g[tid];
    __syncthreads();

    // load x -> fp16 padded smem
    const float* xg = x_vis + (size_t)n * 12288;
    for (int t = tid; t < 12288; t += 512) {
        int ic = t >> 12, r = t & 4095, y = r >> 6, xx = r & 63;
        xs[ic * 4356 + (y + 1) * 66 + xx + 1] = __float2half_rn(xg[t]);
    }
    __syncthreads();

    // ---- conv1: M=1024, N=32, K=48 (3 k16-steps), two M-passes for regs ----
#pragma unroll
    for (int half = 0; half < 2; half++) {
        float acc1[2][4][4];
#pragma unroll
        for (int a = 0; a < 2; a++)
#pragma unroll
            for (int b = 0; b < 4; b++)
#pragma unroll
                for (int c = 0; c < 4; c++) acc1[a][b][c] = 0.f;
        int pbl[2], pbh[2];
#pragma unroll
        for (int mt = 0; mt < 2; mt++) {
            int pl = w * 64 + (half * 2 + mt) * 16 + gid, ph = pl + 8;
            pbl[mt] = ((pl >> 5) * 2) * 66 + (pl & 31) * 2;
            pbh[mt] = ((ph >> 5) * 2) * 66 + (ph & 31) * 2;
        }
#pragma unroll
        for (int ks = 0; ks < 3; ks++) {
            uint4 bv0 = w1f[(ks * 2 + 0) * 32 + lane];
            uint4 bv1 = w1f[(ks * 2 + 1) * 32 + lane];
            int c0 = ks * 16 + tig * 2;
            int o0 = p1t[c0], o1 = p1t[c0 + 8];
#pragma unroll
            for (int mt = 0; mt < 2; mt++) {
                unsigned a0 = *(const unsigned*)&xs[o0 + pbl[mt]];
                unsigned a1 = *(const unsigned*)&xs[o0 + pbh[mt]];
                unsigned a2 = *(const unsigned*)&xs[o1 + pbl[mt]];
                unsigned a3 = *(const unsigned*)&xs[o1 + pbh[mt]];
                MMA_F16(acc1[mt][0], a0, a1, a2, a3, bv0.x, bv0.y);
                MMA_F16(acc1[mt][1], a0, a1, a2, a3, bv0.z, bv0.w);
                MMA_F16(acc1[mt][2], a0, a1, a2, a3, bv1.x, bv1.y);
                MMA_F16(acc1[mt][3], a0, a1, a2, a3, bv1.z, bv1.w);
            }
        }
        // epilogue: relu+bias -> fp16 padded act smem [oc][y+1][x+1]
#pragma unroll
        for (int mt = 0; mt < 2; mt++) {
            int pl = w * 64 + (half * 2 + mt) * 16 + gid, ph = pl + 8;
            int yl = ((pl >> 5) + 1) * 34 + (pl & 31) + 1;
            int yh = ((ph >> 5) + 1) * 34 + (ph & 31) + 1;
#pragma unroll
            for (int nt = 0; nt < 4; nt++) {
                int oc = nt * 8 + 2 * tig;
                act_s[oc * 1156 + yl]       = __float2half_rn(fmaxf(acc1[mt][nt][0] + bi1[oc], 0.f));
                act_s[(oc + 1) * 1156 + yl] = __float2half_rn(fmaxf(acc1[mt][nt][1] + bi1[oc + 1], 0.f));
                act_s[oc * 1156 + yh]       = __float2half_rn(fmaxf(acc1[mt][nt][2] + bi1[oc], 0.f));
                act_s[(oc + 1) * 1156 + yh] = __float2half_rn(fmaxf(acc1[mt][nt][3] + bi1[oc + 1], 0.f));
            }
        }
    }
    __syncthreads();

    // ---- conv2: M=256, N=64, K=512 (32 k16-steps), B fragments from gmem ----
    {
        float acc2[8][4];
#pragma unroll
        for (int a = 0; a < 8; a++)
#pragma unroll
            for (int c = 0; c < 4; c++) acc2[a][c] = 0.f;
        const int pl = w * 16 + gid, ph = pl + 8;
        const int pbl = ((pl >> 4) * 2) * 34 + (pl & 15) * 2;
        const int pbh = ((ph >> 4) * 2) * 34 + (ph & 15) * 2;

#pragma unroll 2
        for (int s = 0; s < 32; s++) {
            int c0 = s * 16 + tig * 2;
            int o0 = p2t[c0], o1 = p2t[c0 + 8];
            const uint4* bp = &g_w2f[s * 128 + lane];
            uint4 b0v = bp[0];
            uint4 b1v = bp[32];
            uint4 b2v = bp[64];
            uint4 b3v = bp[96];
            unsigned a0 = *(const unsigned*)&act_s[o0 + pbl];
            unsigned a1 = *(const unsigned*)&act_s[o0 + pbh];
            unsigned a2 = *(const unsigned*)&act_s[o1 + pbl];
            unsigned a3 = *(const unsigned*)&act_s[o1 + pbh];
            MMA_F16(acc2[0], a0, a1, a2, a3, b0v.x, b0v.y);
            MMA_F16(acc2[1], a0, a1, a2, a3, b0v.z, b0v.w);
            MMA_F16(acc2[2], a0, a1, a2, a3, b1v.x, b1v.y);
            MMA_F16(acc2[3], a0, a1, a2, a3, b1v.z, b1v.w);
            MMA_F16(acc2[4], a0, a1, a2, a3, b2v.x, b2v.y);
            MMA_F16(acc2[5], a0, a1, a2, a3, b2v.z, b2v.w);
            MMA_F16(acc2[6], a0, a1, a2, a3, b3v.x, b3v.y);
            MMA_F16(acc2[7], a0, a1, a2, a3, b3v.z, b3v.w);
        }
        // epilogue -> g_feats fp16
        __half* fo = g_feats + (size_t)n * 16384;
#pragma unroll
        for (int nt = 0; nt < 8; nt++) {
            int oc = nt * 8 + 2 * tig;
            fo[oc * 256 + pl]       = __float2half_rn(fmaxf(acc2[nt][0] + bi2[oc], 0.f));
            fo[(oc + 1) * 256 + pl] = __float2half_rn(fmaxf(acc2[nt][1] + bi2[oc + 1], 0.f));
            fo[oc * 256 + ph]       = __float2half_rn(fmaxf(acc2[nt][2] + bi2[oc], 0.f));
            fo[(oc + 1) * 256 + ph] = __float2half_rn(fmaxf(acc2[nt][3] + bi2[oc + 1], 0.f));
        }
    }
}

// ---------------------------------------------------------------------------
// fp16 GEMM: g_prep[s] = feats(2048 x 1024-chunk) @ bbw-chunk (128 cols).
// Grid (16 M-tiles of 128, KSPLIT=16), 256 threads, reg-prefetch double buffer.
// ---------------------------------------------------------------------------
__global__ __launch_bounds__(256, 2) void gemm_pre_kernel() {
    __shared__ __half As[128 * 40];
    __shared__ uint4  Bs[512];
    const int tid = threadIdx.x, lane = tid & 31, w = tid >> 5;
    const int tig = lane & 3, gid = lane >> 2;
    const int m0 = blockIdx.x * 128;
    const int kb = blockIdx.y * 1024;
    const int arow = tid >> 1, acol = (tid & 1) * 16;

    float acc[16][4];
#pragma unroll
    for (int a = 0; a < 16; a++)
#pragma unroll
        for (int c = 0; c < 4; c++) acc[a][c] = 0.f;

    uint4 pa0, pa1, pb0, pb1;
#define G_LD(kt)                                                               \
    {                                                                          \
        const __half* ap = &g_feats[(size_t)(m0 + arow) * 16384 + kb + (kt) + acol]; \
        pa0 = *(const uint4*)ap;                                               \
        pa1 = *(const uint4*)(ap + 8);                                         \
        const uint4* bp = &g_bwf[((size_t)(kb + (kt)) >> 4) * 256 + tid];      \
        pb0 = bp[0];                                                           \
        pb1 = bp[256];                                                         \
    }
#define G_ST()                                                                 \
    {                                                                          \
        *(uint4*)&As[arow * 40 + acol] = pa0;                                  \
        *(uint4*)&As[arow * 40 + acol + 8] = pa1;                              \
        Bs[tid] = pb0;                                                         \
        Bs[tid + 256] = pb1;                                                   \
    }

    G_LD(0);
    G_ST();
    __syncthreads();

    for (int it = 0; it < 32; it++) {
        if (it < 31) G_LD((it + 1) * 32);
#pragma unroll
        for (int ks2 = 0; ks2 < 2; ks2++) {
            const __half* ap = &As[(w * 16 + gid) * 40 + ks2 * 16 + tig * 2];
            unsigned a0 = *(const unsigned*)ap;
            unsigned a1 = *(const unsigned*)(ap + 8 * 40);
            unsigned a2 = *(const unsigned*)(ap + 8);
            unsigned a3 = *(const unsigned*)(ap + 8 * 40 + 8);
#pragma unroll
            for (int ntp = 0; ntp < 8; ntp++) {
                uint4 bv = Bs[ks2 * 256 + ntp * 32 + lane];
                MMA_F16(acc[ntp * 2], a0, a1, a2, a3, bv.x, bv.y);
                MMA_F16(acc[ntp * 2 + 1], a0, a1, a2, a3, bv.z, bv.w);
            }
        }
        __syncthreads();
        if (it < 31) {
            G_ST();
            __syncthreads();
        }
    }

    float* op = g_prep + (size_t)blockIdx.y * (NT * 128);
    const int r0 = m0 + w * 16 + gid;
#pragma unroll
    for (int nt = 0; nt < 16; nt++) {
        *(float2*)&op[(size_t)r0 * 128 + nt * 8 + 2 * tig] = make_float2(acc[nt][0], acc[nt][1]);
        *(float2*)&op[(size_t)(r0 + 8) * 128 + nt * 8 + 2 * tig] = make_float2(acc[nt][2], acc[nt][3]);
    }
}

// ---------------------------------------------------------------------------
// CfC recurrent scan + logits. One CTA per batch, 768 threads.
// Register-resident weights WITHOUT spills:
//   phase0: tid<512, 4 lanes/output (w0[16]), shfl_xor(1,2); split-K partials
//           folded in (each lane sums 4 of 16 g_prep slices, prefetched).
//   phase1: all 768 threads, 4 lanes/output (192*4=768, w1r[32]), shfl_xor(1,2).
// Persistent regs ~48 weights + ~25 working < 80-reg cap at 768 thr -> no LDL.
// ---------------------------------------------------------------------------
__global__ __launch_bounds__(768, 1) void recur_kernel(
                             const float* __restrict__ hx,
                             const float* __restrict__ bbw,
                             const float* __restrict__ bbb,
                             const float* __restrict__ f1w, const float* __restrict__ f1b,
                             const float* __restrict__ f2w, const float* __restrict__ f2b,
                             const float* __restrict__ taw, const float* __restrict__ tab,
                             const float* __restrict__ tbw, const float* __restrict__ tbb,
                             const float* __restrict__ ow,  const float* __restrict__ ob,
                             float* __restrict__ out, int out_size) {
    __shared__ float hs[64];
    __shared__ float bbs[128];
    __shared__ float heads[192];
    __shared__ float outs[64 * 68];
    __shared__ float outw[8 * 68];
    __shared__ float obs[8];
    const int b = blockIdx.x, tid = threadIdx.x;

    // phase0 ownership: output j0 (0..127), K-part p0 (0..3) of 16
    const int j0 = (tid >> 2) & 127, p0 = tid & 3;
    float w0[16];
    float bias0 = 0.f;
    if (tid < 512) {
#pragma unroll
        for (int kk = 0; kk < 16; kk++)
            w0[kk] = bbw[(size_t)(16384 + p0 * 16 + kk) * 128 + j0];
        bias0 = bbb[j0];
    }

    // phase1 ownership: output j1 (0..191), K-part p1 (0..3) of 32
    const int j1 = tid >> 2, p1 = tid & 3;
    const int m = j1 >> 6;          // 0=ff1, 1=ff2, 2=merged gate
    const int i = j1 & 63;
    float w1r[32];
    float bias1;
    if (m == 2) {
#pragma unroll 8
        for (int kk = 0; kk < 32; kk++) {
            int k = p1 * 32 + kk;
            w1r[kk] = taw[k * 64 + i] + tbw[k * 64 + i];
        }
        bias1 = tab[i] + tbb[i];
    } else {
        const float* Wm = (m == 1) ? f2w : f1w;
#pragma unroll 8
        for (int kk = 0; kk < 32; kk++)
            w1r[kk] = Wm[(p1 * 32 + kk) * 64 + i];
        bias1 = (m == 1) ? f2b[i] : f1b[i];
    }

    if (tid < 512) {
        int s = tid >> 3, o = tid & 7;
        outw[o * 68 + s] = ow[s * 8 + o];
    }
    if (tid < 8)  obs[tid] = ob[tid];
    if (tid < 64) hs[tid] = hx[b * 64 + tid];
    __syncthreads();

    const size_t base0 = (size_t)(b * TT) * 128 + j0;
    float nxt[4] = {0.f, 0.f, 0.f, 0.f};
    if (tid < 512) {
#pragma unroll
        for (int q = 0; q < 4; q++)
            nxt[q] = g_prep[(size_t)(p0 + 4 * q) * (NT * 128) + base0];
    }

    for (int ts = 0; ts < TT; ts++) {
        // phase 0: bb = lecun_tanh(pre + h @ Wh), 4 lanes per output
        if (tid < 512) {
            float a0 = (nxt[0] + nxt[1]) + (nxt[2] + nxt[3]), a1 = 0.f;
            if (ts < TT - 1) {
#pragma unroll
                for (int q = 0; q < 4; q++)
                    nxt[q] = g_prep[(size_t)(p0 + 4 * q) * (NT * 128) + base0 + (ts + 1) * 128];
            }
            const float4* h4 = (const float4*)(hs + p0 * 16);
#pragma unroll
            for (int q = 0; q < 4; q++) {
                float4 hv = h4[q];
                a0 += w0[q * 4 + 0] * hv.x + w0[q * 4 + 1] * hv.y;
                a1 += w0[q * 4 + 2] * hv.z + w0[q * 4 + 3] * hv.w;
            }
            float d = a0 + a1;
            d += __shfl_xor_sync(0xffffffffu, d, 1);
            d += __shfl_xor_sync(0xffffffffu, d, 2);
            if (p0 == 0)
                bbs[j0] = 1.7159f * fast_tanh(0.666f * (d + bias0));
        }
        __syncthreads();
        // phase 1: heads (ff1/ff2 tanh'd; merged gate linear), 4 lanes per output
        {
            float a0 = 0.f, a1 = 0.f;
            const float4* b4 = (const float4*)(bbs + p1 * 32);
#pragma unroll
            for (int q = 0; q < 8; q++) {
                float4 bv = b4[q];
                a0 += w1r[q * 4 + 0] * bv.x + w1r[q * 4 + 1] * bv.y;
                a1 += w1r[q * 4 + 2] * bv.z + w1r[q * 4 + 3] * bv.w;
            }
            float d = a0 + a1;
            d += __shfl_xor_sync(0xffffffffu, d, 1);
            d += __shfl_xor_sync(0xffffffffu, d, 2);
            if (p1 == 0) {
                d += bias1;
                heads[j1] = (m < 2) ? fast_tanh(d) : d;
            }
        }
        __syncthreads();
        // phase 2: gated interpolation
        if (tid < 64) {
            float ti = fast_sig(heads[128 + tid]);
            float hn = heads[tid] * (1.f - ti) + ti * heads[64 + tid];
            hs[tid] = hn;
            outs[ts * 68 + tid] = hn;
        }
        __syncthreads();
    }

    // logits epilogue: 512 outputs, one per thread
    if (tid < 512) {
        int s = tid >> 3, o = tid & 7;
        float a0 = obs[o], a1 = 0.f;
        const float* r = &outs[s * 68];
        const float* wv = &outw[o * 68];
#pragma unroll
        for (int k = 0; k < 64; k += 2) {
            a0 += r[k] * wv[k];
            a1 += r[k + 1] * wv[k + 1];
        }
        out[(size_t)(b * TT + s) * 8 + o] = a0 + a1;
    }
    if (out_size >= 18432 && tid < 64) out[16384 + b * 64 + tid] = hs[tid];
}

// ---------------------------------------------------------------------------
extern "C" void kernel_launch(void* const* d_in, const int* in_sizes, int n_in,
                              void* d_out, int out_size) {
    const float* x_vis   = (const float*)d_in[0];
    const float* hx      = (const float*)d_in[1];
    const float* conv1_w = (const float*)d_in[2];
    const float* conv1_b = (const float*)d_in[3];
    const float* conv2_w = (const float*)d_in[4];
    const float* conv2_b = (const float*)d_in[5];
    const float* bb_w    = (const float*)d_in[6];
    const float* bb_b    = (const float*)d_in[7];
    const float* ff1_w   = (const float*)d_in[8];
    const float* ff1_b   = (const float*)d_in[9];
    const float* ff2_w   = (const float*)d_in[10];
    const float* ff2_b   = (const float*)d_in[11];
    const float* ta_w    = (const float*)d_in[12];
    const float* ta_b    = (const float*)d_in[13];
    const float* tb_w    = (const float*)d_in[14];
    const float* tb_b    = (const float*)d_in[15];
    const float* out_w   = (const float*)d_in[16];
    const float* out_b   = (const float*)d_in[17];
    float* out = (float*)d_out;

    const size_t smf = CB_TOT;                             // 105824 B (occ 2)

    cudaFuncSetAttribute(fused_conv_kernel, cudaFuncAttributeMaxDynamicSharedMemorySize, (int)smf);

    prep_kernel<<<1041, 256>>>(conv1_w, conv2_w, bb_w);
    fused_conv_kernel<<<NT, 512, smf>>>(x_vis, conv1_b, conv2_b);
    gemm_pre_kernel<<<dim3(16, KSPLIT), 256>>>();
    recur_kernel<<<BB, 768>>>(hx, bb_w, bb_b,
                              ff1_w, ff1_b, ff2_w, ff2_b,
                              ta_w, ta_b, tb_w, tb_b,
                              out_w, out_b, out, out_size);
}

// round 12
// speedup vs baseline: 1.2304x; 1.2304x over previous
#include <cuda_runtime.h>
#include <cuda_fp16.h>
#include <math.h>

#define BB 32
#define TT 64
#define NT 2048        // BB*TT images
#define KSPLIT 16

// Scratch (static device globals — allocation-free kernel_launch)
__device__ __half g_feats[(size_t)NT * 16384];        // conv2 out fp16: [n][oc*256+p]
__device__ float  g_prep[(size_t)KSPLIT * NT * 128];  // split-K partials (fp32)
__device__ uint4  g_w1f[192];                          // conv1 B-fragments (3 ks x 2 ntp x 32)
__device__ uint4  g_w2f[4096];                         // conv2 B-fragments (32 ks x 4 ntp x 32)
__device__ uint4  g_bwf[262144];                       // bb_w B-fragments (1024 ks x 8 ntp x 32)

// ---------------------------------------------------------------------------
// helpers
// ---------------------------------------------------------------------------
__device__ __forceinline__ unsigned h2pack(float lo, float hi) {
    __half2 h = __floats2half2_rn(lo, hi);
    return *(unsigned*)&h;
}

#define MMA_F16(d, a0, a1, a2, a3, b0, b1)                                    \
    asm volatile("mma.sync.aligned.m16n8k16.row.col.f32.f16.f16.f32 "         \
                 "{%0,%1,%2,%3}, {%4,%5,%6,%7}, {%8,%9}, {%0,%1,%2,%3};"      \
                 : "+f"(d[0]), "+f"(d[1]), "+f"(d[2]), "+f"(d[3])             \
                 : "r"(a0), "r"(a1), "r"(a2), "r"(a3), "r"(b0), "r"(b1))

__device__ __forceinline__ float fast_tanh(float x) {
    float e = __expf(2.f * x);
    return 1.f - __fdividef(2.f, e + 1.f);
}
__device__ __forceinline__ float fast_sig(float x) {
    return __fdividef(1.f, 1.f + __expf(-x));
}

// ---------------------------------------------------------------------------
// prep: pack all B operands into m16n8k16 fragment layout (fp16)
// blocks 0..1023: bbw kstep tiles. blocks 1024..1039: w2 (spread, no straggler).
// block 1040: w1.
// ---------------------------------------------------------------------------
__global__ void prep_kernel(const float* __restrict__ w1, const float* __restrict__ w2,
                            const float* __restrict__ bbw) {
    const int blk = blockIdx.x, t = threadIdx.x;
    if (blk < 1024) {
        __shared__ float sm[2048];            // 16 k-rows x 128 n
        const float4* src = (const float4*)(bbw + (size_t)blk * 16 * 128);
        for (int i = t; i < 512; i += 256) ((float4*)sm)[i] = src[i];
        __syncthreads();
        int ntp = t >> 5, lane = t & 31;
        int tig = lane & 3, gid = lane >> 2;
        int c = tig * 2, n = ntp * 16 + gid;
        uint4 v;
        v.x = h2pack(sm[c * 128 + n],           sm[(c + 1) * 128 + n]);
        v.y = h2pack(sm[(c + 8) * 128 + n],     sm[(c + 9) * 128 + n]);
        v.z = h2pack(sm[c * 128 + n + 8],       sm[(c + 1) * 128 + n + 8]);
        v.w = h2pack(sm[(c + 8) * 128 + n + 8], sm[(c + 9) * 128 + n + 8]);
        g_bwf[blk * 256 + t] = v;
    } else if (blk < 1040) {
        int idx = (blk - 1024) * 256 + t;     // 4096 total, 16 blocks
        int ks = idx >> 7, ntp = (idx >> 5) & 3, lane = idx & 31;
        int tig = lane & 3, gid = lane >> 2;
        int c = ks * 16 + tig * 2, n = ntp * 16 + gid;
        uint4 v;
        v.x = h2pack(w2[n * 512 + c],           w2[n * 512 + c + 1]);
        v.y = h2pack(w2[n * 512 + c + 8],       w2[n * 512 + c + 9]);
        v.z = h2pack(w2[(n + 8) * 512 + c],     w2[(n + 8) * 512 + c + 1]);
        v.w = h2pack(w2[(n + 8) * 512 + c + 8], w2[(n + 8) * 512 + c + 9]);
        g_w2f[idx] = v;
    } else {
        if (t < 192) {
            int ks = t >> 6, ntp = (t >> 5) & 1, lane = t & 31;
            int tig = lane & 3, gid = lane >> 2;
            int c = ks * 16 + tig * 2, n = ntp * 16 + gid;
            uint4 v;
            v.x = h2pack(w1[n * 48 + c],           w1[n * 48 + c + 1]);
            v.y = h2pack(w1[n * 48 + c + 8],       w1[n * 48 + c + 9]);
            v.z = h2pack(w1[(n + 8) * 48 + c],     w1[(n + 8) * 48 + c + 1]);
            v.w = h2pack(w1[(n + 8) * 48 + c + 8], w1[(n + 8) * 48 + c + 9]);
            g_w1f[t] = v;
        }
    }
}

// ---------------------------------------------------------------------------
// Fused conv1+conv2 per image, fp16 m16n8k16. One CTA per image, 512 threads.
// Occupancy 2: w2 B-fragments are read straight from gmem (L1/L2-resident).
// ---------------------------------------------------------------------------
#define CB_ACT 0
#define CB_X   73984
#define CB_W1  100128
#define CB_P2  103200
#define CB_P1  105248
#define CB_BI1 105440
#define CB_BI2 105568
#define CB_TOT 105824

__global__ __launch_bounds__(512, 2) void fused_conv_kernel(
    const float* __restrict__ x_vis,
    const float* __restrict__ b1g, const float* __restrict__ b2g) {
    extern __shared__ char smc[];
    __half* act_s = (__half*)(smc + CB_ACT);
    __half* xs    = (__half*)(smc + CB_X);
    uint4*  w1f   = (uint4*)(smc + CB_W1);
    int*    p2t   = (int*)(smc + CB_P2);
    int*    p1t   = (int*)(smc + CB_P1);
    float*  bi1   = (float*)(smc + CB_BI1);
    float*  bi2   = (float*)(smc + CB_BI2);

    const int n = blockIdx.x, tid = threadIdx.x;
    const int lane = tid & 31, w = tid >> 5;
    const int tig = lane & 3, gid = lane >> 2;

    // zero act + x regions (6258 uint4)
    {
        uint4 z = make_uint4(0, 0, 0, 0);
        uint4* zp = (uint4*)smc;
        for (int t = tid; t < 6258; t += 512) zp[t] = z;
    }
    if (tid < 48)  p1t[tid] = (tid >> 4) * 4356 + ((tid >> 2) & 3) * 66 + (tid & 3);
    if (tid < 512) p2t[tid] = (tid >> 4) * 1156 + ((tid >> 2) & 3) * 34 + (tid & 3);
    if (tid < 192) w1f[tid] = g_w1f[tid];
    if (tid < 32) bi1[tid] = b1g[tid];
    if (tid < 64) bi2[tid] = b2g[tid];
    __syncthreads();

    // load x -> fp16 padded smem
    const float* xg = x_vis + (size_t)n * 12288;
    for (int t = tid; t < 12288; t += 512) {
        int ic = t >> 12, r = t & 4095, y = r >> 6, xx = r & 63;
        xs[ic * 4356 + (y + 1) * 66 + xx + 1] = __float2half_rn(xg[t]);
    }
    __syncthreads();

    // ---- conv1: M=1024, N=32, K=48 (3 k16-steps), two M-passes for regs ----
#pragma unroll
    for (int half = 0; half < 2; half++) {
        float acc1[2][4][4];
#pragma unroll
        for (int a = 0; a < 2; a++)
#pragma unroll
            for (int b = 0; b < 4; b++)
#pragma unroll
                for (int c = 0; c < 4; c++) acc1[a][b][c] = 0.f;
        int pbl[2], pbh[2];
#pragma unroll
        for (int mt = 0; mt < 2; mt++) {
            int pl = w * 64 + (half * 2 + mt) * 16 + gid, ph = pl + 8;
            pbl[mt] = ((pl >> 5) * 2) * 66 + (pl & 31) * 2;
            pbh[mt] = ((ph >> 5) * 2) * 66 + (ph & 31) * 2;
        }
#pragma unroll
        for (int ks = 0; ks < 3; ks++) {
            uint4 bv0 = w1f[(ks * 2 + 0) * 32 + lane];
            uint4 bv1 = w1f[(ks * 2 + 1) * 32 + lane];
            int c0 = ks * 16 + tig * 2;
            int o0 = p1t[c0], o1 = p1t[c0 + 8];
#pragma unroll
            for (int mt = 0; mt < 2; mt++) {
                unsigned a0 = *(const unsigned*)&xs[o0 + pbl[mt]];
                unsigned a1 = *(const unsigned*)&xs[o0 + pbh[mt]];
                unsigned a2 = *(const unsigned*)&xs[o1 + pbl[mt]];
                unsigned a3 = *(const unsigned*)&xs[o1 + pbh[mt]];
                MMA_F16(acc1[mt][0], a0, a1, a2, a3, bv0.x, bv0.y);
                MMA_F16(acc1[mt][1], a0, a1, a2, a3, bv0.z, bv0.w);
                MMA_F16(acc1[mt][2], a0, a1, a2, a3, bv1.x, bv1.y);
                MMA_F16(acc1[mt][3], a0, a1, a2, a3, bv1.z, bv1.w);
            }
        }
        // epilogue: relu+bias -> fp16 padded act smem [oc][y+1][x+1]
#pragma unroll
        for (int mt = 0; mt < 2; mt++) {
            int pl = w * 64 + (half * 2 + mt) * 16 + gid, ph = pl + 8;
            int yl = ((pl >> 5) + 1) * 34 + (pl & 31) + 1;
            int yh = ((ph >> 5) + 1) * 34 + (ph & 31) + 1;
#pragma unroll
            for (int nt = 0; nt < 4; nt++) {
                int oc = nt * 8 + 2 * tig;
                act_s[oc * 1156 + yl]       = __float2half_rn(fmaxf(acc1[mt][nt][0] + bi1[oc], 0.f));
                act_s[(oc + 1) * 1156 + yl] = __float2half_rn(fmaxf(acc1[mt][nt][1] + bi1[oc + 1], 0.f));
                act_s[oc * 1156 + yh]       = __float2half_rn(fmaxf(acc1[mt][nt][2] + bi1[oc], 0.f));
                act_s[(oc + 1) * 1156 + yh] = __float2half_rn(fmaxf(acc1[mt][nt][3] + bi1[oc + 1], 0.f));
            }
        }
    }
    __syncthreads();

    // ---- conv2: M=256, N=64, K=512 (32 k16-steps), B fragments from gmem ----
    {
        float acc2[8][4];
#pragma unroll
        for (int a = 0; a < 8; a++)
#pragma unroll
            for (int c = 0; c < 4; c++) acc2[a][c] = 0.f;
        const int pl = w * 16 + gid, ph = pl + 8;
        const int pbl = ((pl >> 4) * 2) * 34 + (pl & 15) * 2;
        const int pbh = ((ph >> 4) * 2) * 34 + (ph & 15) * 2;

#pragma unroll 2
        for (int s = 0; s < 32; s++) {
            int c0 = s * 16 + tig * 2;
            int o0 = p2t[c0], o1 = p2t[c0 + 8];
            const uint4* bp = &g_w2f[s * 128 + lane];
            uint4 b0v = bp[0];
            uint4 b1v = bp[32];
            uint4 b2v = bp[64];
            uint4 b3v = bp[96];
            unsigned a0 = *(const unsigned*)&act_s[o0 + pbl];
            unsigned a1 = *(const unsigned*)&act_s[o0 + pbh];
            unsigned a2 = *(const unsigned*)&act_s[o1 + pbl];
            unsigned a3 = *(const unsigned*)&act_s[o1 + pbh];
            MMA_F16(acc2[0], a0, a1, a2, a3, b0v.x, b0v.y);
            MMA_F16(acc2[1], a0, a1, a2, a3, b0v.z, b0v.w);
            MMA_F16(acc2[2], a0, a1, a2, a3, b1v.x, b1v.y);
            MMA_F16(acc2[3], a0, a1, a2, a3, b1v.z, b1v.w);
            MMA_F16(acc2[4], a0, a1, a2, a3, b2v.x, b2v.y);
            MMA_F16(acc2[5], a0, a1, a2, a3, b2v.z, b2v.w);
            MMA_F16(acc2[6], a0, a1, a2, a3, b3v.x, b3v.y);
            MMA_F16(acc2[7], a0, a1, a2, a3, b3v.z, b3v.w);
        }
        // epilogue -> g_feats fp16
        __half* fo = g_feats + (size_t)n * 16384;
#pragma unroll
        for (int nt = 0; nt < 8; nt++) {
            int oc = nt * 8 + 2 * tig;
            fo[oc * 256 + pl]       = __float2half_rn(fmaxf(acc2[nt][0] + bi2[oc], 0.f));
            fo[(oc + 1) * 256 + pl] = __float2half_rn(fmaxf(acc2[nt][1] + bi2[oc + 1], 0.f));
            fo[oc * 256 + ph]       = __float2half_rn(fmaxf(acc2[nt][2] + bi2[oc], 0.f));
            fo[(oc + 1) * 256 + ph] = __float2half_rn(fmaxf(acc2[nt][3] + bi2[oc + 1], 0.f));
        }
    }
}

// ---------------------------------------------------------------------------
// fp16 GEMM: g_prep[s] = feats(2048 x 1024-chunk) @ bbw-chunk (128 cols).
// Grid (16 M-tiles of 128, KSPLIT=16), 256 threads, reg-prefetch double buffer.
// ---------------------------------------------------------------------------
__global__ __launch_bounds__(256, 2) void gemm_pre_kernel() {
    __shared__ __half As[128 * 40];
    __shared__ uint4  Bs[512];
    const int tid = threadIdx.x, lane = tid & 31, w = tid >> 5;
    const int tig = lane & 3, gid = lane >> 2;
    const int m0 = blockIdx.x * 128;
    const int kb = blockIdx.y * 1024;
    const int arow = tid >> 1, acol = (tid & 1) * 16;

    float acc[16][4];
#pragma unroll
    for (int a = 0; a < 16; a++)
#pragma unroll
        for (int c = 0; c < 4; c++) acc[a][c] = 0.f;

    uint4 pa0, pa1, pb0, pb1;
#define G_LD(kt)                                                               \
    {                                                                          \
        const __half* ap = &g_feats[(size_t)(m0 + arow) * 16384 + kb + (kt) + acol]; \
        pa0 = *(const uint4*)ap;                                               \
        pa1 = *(const uint4*)(ap + 8);                                         \
        const uint4* bp = &g_bwf[((size_t)(kb + (kt)) >> 4) * 256 + tid];      \
        pb0 = bp[0];                                                           \
        pb1 = bp[256];                                                         \
    }
#define G_ST()                                                                 \
    {                                                                          \
        *(uint4*)&As[arow * 40 + acol] = pa0;                                  \
        *(uint4*)&As[arow * 40 + acol + 8] = pa1;                              \
        Bs[tid] = pb0;                                                         \
        Bs[tid + 256] = pb1;                                                   \
    }

    G_LD(0);
    G_ST();
    __syncthreads();

    for (int it = 0; it < 32; it++) {
        if (it < 31) G_LD((it + 1) * 32);
#pragma unroll
        for (int ks2 = 0; ks2 < 2; ks2++) {
            const __half* ap = &As[(w * 16 + gid) * 40 + ks2 * 16 + tig * 2];
            unsigned a0 = *(const unsigned*)ap;
            unsigned a1 = *(const unsigned*)(ap + 8 * 40);
            unsigned a2 = *(const unsigned*)(ap + 8);
            unsigned a3 = *(const unsigned*)(ap + 8 * 40 + 8);
#pragma unroll
            for (int ntp = 0; ntp < 8; ntp++) {
                uint4 bv = Bs[ks2 * 256 + ntp * 32 + lane];
                MMA_F16(acc[ntp * 2], a0, a1, a2, a3, bv.x, bv.y);
                MMA_F16(acc[ntp * 2 + 1], a0, a1, a2, a3, bv.z, bv.w);
            }
        }
        __syncthreads();
        if (it < 31) {
            G_ST();
            __syncthreads();
        }
    }

    float* op = g_prep + (size_t)blockIdx.y * (NT * 128);
    const int r0 = m0 + w * 16 + gid;
#pragma unroll
    for (int nt = 0; nt < 16; nt++) {
        *(float2*)&op[(size_t)r0 * 128 + nt * 8 + 2 * tig] = make_float2(acc[nt][0], acc[nt][1]);
        *(float2*)&op[(size_t)(r0 + 8) * 128 + nt * 8 + 2 * tig] = make_float2(acc[nt][2], acc[nt][3]);
    }
}

// ---------------------------------------------------------------------------
// CfC recurrent scan + logits. One CTA per batch, 512 threads.
// Register-resident weights stored as HALF2 (fp16) to stay far below the
// 128-reg cap -> no spills (R10 pinned 127 regs = spill-bound at 99.6us).
// Math in fp32 via __half22float2. Split-K partial sum folded into phase0's
// shfl reduction (each of 4 lanes sums 4 of 16 g_prep slices, prefetched).
// ---------------------------------------------------------------------------
__global__ __launch_bounds__(512, 1) void recur_kernel(
                             const float* __restrict__ hx,
                             const float* __restrict__ bbw,
                             const float* __restrict__ bbb,
                             const float* __restrict__ f1w, const float* __restrict__ f1b,
                             const float* __restrict__ f2w, const float* __restrict__ f2b,
                             const float* __restrict__ taw, const float* __restrict__ tab,
                             const float* __restrict__ tbw, const float* __restrict__ tbb,
                             const float* __restrict__ ow,  const float* __restrict__ ob,
                             float* __restrict__ out, int out_size) {
    __shared__ float hs[64];
    __shared__ float bbs[128];
    __shared__ float heads[192];
    __shared__ float outs[64 * 68];
    __shared__ float outw[8 * 68];
    __shared__ float obs[8];
    const int b = blockIdx.x, tid = threadIdx.x;

    // phase0 ownership: output j0 (0..127), K-part p0 (0..3) of 16
    const int j0 = tid >> 2, p0 = tid & 3;
    __half2 w0h[8];
#pragma unroll
    for (int q = 0; q < 8; q++)
        w0h[q] = __floats2half2_rn(bbw[(size_t)(16384 + p0 * 16 + 2 * q) * 128 + j0],
                                   bbw[(size_t)(16384 + p0 * 16 + 2 * q + 1) * 128 + j0]);
    const float bias0 = bbb[j0];

    // phase1 ownership: output j1 (0..191), K-part p1 (0..1) of 64
    const int j1 = tid >> 1, p1 = tid & 1;
    const int m = (tid < 384) ? (j1 >> 6) : 0;
    const int i = j1 & 63;
    __half2 w1h[32];
    float bias1 = 0.f;
    if (tid < 384) {
        if (m == 2) {
#pragma unroll 8
            for (int q = 0; q < 32; q++) {
                int k = p1 * 64 + 2 * q;
                w1h[q] = __floats2half2_rn(taw[k * 64 + i] + tbw[k * 64 + i],
                                           taw[(k + 1) * 64 + i] + tbw[(k + 1) * 64 + i]);
            }
            bias1 = tab[i] + tbb[i];
        } else {
            const float* Wm = (m == 1) ? f2w : f1w;
#pragma unroll 8
            for (int q = 0; q < 32; q++) {
                int k = p1 * 64 + 2 * q;
                w1h[q] = __floats2half2_rn(Wm[k * 64 + i], Wm[(k + 1) * 64 + i]);
            }
            bias1 = (m == 1) ? f2b[i] : f1b[i];
        }
    }

    {
        int s = tid >> 3, o = tid & 7;
        outw[o * 68 + s] = ow[s * 8 + o];
    }
    if (tid < 8)  obs[tid] = ob[tid];
    if (tid < 64) hs[tid] = hx[b * 64 + tid];
    __syncthreads();

    const size_t base0 = (size_t)(b * TT) * 128 + j0;
    float nxt[4];
#pragma unroll
    for (int q = 0; q < 4; q++)
        nxt[q] = g_prep[(size_t)(p0 + 4 * q) * (NT * 128) + base0];

    for (int ts = 0; ts < TT; ts++) {
        float cur = (nxt[0] + nxt[1]) + (nxt[2] + nxt[3]);
        if (ts < TT - 1) {
#pragma unroll
            for (int q = 0; q < 4; q++)
                nxt[q] = g_prep[(size_t)(p0 + 4 * q) * (NT * 128) + base0 + (ts + 1) * 128];
        }
        // phase 0: bb = lecun_tanh(pre + h @ Wh), 4 lanes per output
        {
            float a0 = cur, a1 = 0.f;
            const float4* h4 = (const float4*)(hs + p0 * 16);
#pragma unroll
            for (int q = 0; q < 4; q++) {
                float4 hv = h4[q];
                float2 wa = __half22float2(w0h[2 * q]);
                float2 wb = __half22float2(w0h[2 * q + 1]);
                a0 += wa.x * hv.x + wa.y * hv.y;
                a1 += wb.x * hv.z + wb.y * hv.w;
            }
            float d = a0 + a1;
            d += __shfl_xor_sync(0xffffffffu, d, 1);
            d += __shfl_xor_sync(0xffffffffu, d, 2);
            if (p0 == 0)
                bbs[j0] = 1.7159f * fast_tanh(0.666f * (d + bias0));
        }
        __syncthreads();
        // phase 1: heads (ff1/ff2 tanh'd; merged gate linear), 2 lanes per output
        if (tid < 384) {
            float a0 = 0.f, a1 = 0.f, a2 = 0.f, a3 = 0.f;
            const float4* b4 = (const float4*)(bbs + p1 * 64);
#pragma unroll
            for (int q = 0; q < 16; q += 2) {
                float4 bv = b4[q];
                float2 wa = __half22float2(w1h[2 * q]);
                float2 wb = __half22float2(w1h[2 * q + 1]);
                a0 += wa.x * bv.x + wa.y * bv.y;
                a1 += wb.x * bv.z + wb.y * bv.w;
                float4 bv2 = b4[q + 1];
                float2 wc = __half22float2(w1h[2 * q + 2]);
                float2 wd = __half22float2(w1h[2 * q + 3]);
                a2 += wc.x * bv2.x + wc.y * bv2.y;
                a3 += wd.x * bv2.z + wd.y * bv2.w;
            }
            float d = (a0 + a1) + (a2 + a3);
            d += __shfl_xor_sync(0xffffffffu, d, 1);
            if (p1 == 0) {
                d += bias1;
                heads[j1] = (m < 2) ? fast_tanh(d) : d;
            }
        }
        __syncthreads();
        // phase 2: gated interpolation
        if (tid < 64) {
            float ti = fast_sig(heads[128 + tid]);
            float hn = heads[tid] * (1.f - ti) + ti * heads[64 + tid];
            hs[tid] = hn;
            outs[ts * 68 + tid] = hn;
        }
        __syncthreads();
    }

    // logits epilogue: 512 outputs, one per thread
    {
        int s = tid >> 3, o = tid & 7;
        float a0 = obs[o], a1 = 0.f;
        const float* r = &outs[s * 68];
        const float* wv = &outw[o * 68];
#pragma unroll
        for (int k = 0; k < 64; k += 2) {
            a0 += r[k] * wv[k];
            a1 += r[k + 1] * wv[k + 1];
        }
        out[(size_t)(b * TT + s) * 8 + o] = a0 + a1;
    }
    if (out_size >= 18432 && tid < 64) out[16384 + b * 64 + tid] = hs[tid];
}

// ---------------------------------------------------------------------------
extern "C" void kernel_launch(void* const* d_in, const int* in_sizes, int n_in,
                              void* d_out, int out_size) {
    const float* x_vis   = (const float*)d_in[0];
    const float* hx      = (const float*)d_in[1];
    const float* conv1_w = (const float*)d_in[2];
    const float* conv1_b = (const float*)d_in[3];
    const float* conv2_w = (const float*)d_in[4];
    const float* conv2_b = (const float*)d_in[5];
    const float* bb_w    = (const float*)d_in[6];
    const float* bb_b    = (const float*)d_in[7];
    const float* ff1_w   = (const float*)d_in[8];
    const float* ff1_b   = (const float*)d_in[9];
    const float* ff2_w   = (const float*)d_in[10];
    const float* ff2_b   = (const float*)d_in[11];
    const float* ta_w    = (const float*)d_in[12];
    const float* ta_b    = (const float*)d_in[13];
    const float* tb_w    = (const float*)d_in[14];
    const float* tb_b    = (const float*)d_in[15];
    const float* out_w   = (const float*)d_in[16];
    const float* out_b   = (const float*)d_in[17];
    float* out = (float*)d_out;

    const size_t smf = CB_TOT;                             // 105824 B (occ 2)

    cudaFuncSetAttribute(fused_conv_kernel, cudaFuncAttributeMaxDynamicSharedMemorySize, (int)smf);

    prep_kernel<<<1041, 256>>>(conv1_w, conv2_w, bb_w);
    fused_conv_kernel<<<NT, 512, smf>>>(x_vis, conv1_b, conv2_b);
    gemm_pre_kernel<<<dim3(16, KSPLIT), 256>>>();
    recur_kernel<<<BB, 512>>>(hx, bb_w, bb_b,
                              ff1_w, ff1_b, ff2_w, ff2_b,
                              ta_w, ta_b, tb_w, tb_b,
                              out_w, out_b, out, out_size);
}

// round 15
// speedup vs baseline: 1.2515x; 1.0172x over previous
#include <cuda_runtime.h>
#include <cuda_fp16.h>
#include <math.h>

#define BB 32
#define TT 64
#define NT 2048        // BB*TT images
#define KSPLIT 16

// Scratch (static device globals — allocation-free kernel_launch)
__device__ __half g_feats[(size_t)NT * 16384];        // conv2 out fp16: [n][oc*256+p]
__device__ float  g_prep[(size_t)KSPLIT * NT * 128];  // split-K partials (fp32)
__device__ uint4  g_w1f[192];                          // conv1 B-fragments (3 ks x 2 ntp x 32)
__device__ uint4  g_w2f[4096];                         // conv2 B-fragments (32 ks x 4 ntp x 32)
__device__ uint4  g_bwf[262144];                       // bb_w B-fragments (1024 ks x 8 ntp x 32)

// ---------------------------------------------------------------------------
// helpers
// ---------------------------------------------------------------------------
__device__ __forceinline__ unsigned h2pack(float lo, float hi) {
    __half2 h = __floats2half2_rn(lo, hi);
    return *(unsigned*)&h;
}

#define MMA_F16(d, a0, a1, a2, a3, b0, b1)                                    \
    asm volatile("mma.sync.aligned.m16n8k16.row.col.f32.f16.f16.f32 "         \
                 "{%0,%1,%2,%3}, {%4,%5,%6,%7}, {%8,%9}, {%0,%1,%2,%3};"      \
                 : "+f"(d[0]), "+f"(d[1]), "+f"(d[2]), "+f"(d[3])             \
                 : "r"(a0), "r"(a1), "r"(a2), "r"(a3), "r"(b0), "r"(b1))

__device__ __forceinline__ float fast_tanh(float x) {
    float e = __expf(2.f * x);
    return 1.f - __fdividef(2.f, e + 1.f);
}
__device__ __forceinline__ float fast_sig(float x) {
    return __fdividef(1.f, 1.f + __expf(-x));
}

// ---------------------------------------------------------------------------
// prep: pack all B operands into m16n8k16 fragment layout (fp16)
// blocks 0..1023: bbw kstep tiles. blocks 1024..1039: w2 (spread, no straggler).
// block 1040: w1.
// ---------------------------------------------------------------------------
__global__ void prep_kernel(const float* __restrict__ w1, const float* __restrict__ w2,
                            const float* __restrict__ bbw) {
    const int blk = blockIdx.x, t = threadIdx.x;
    if (blk < 1024) {
        __shared__ float sm[2048];            // 16 k-rows x 128 n
        const float4* src = (const float4*)(bbw + (size_t)blk * 16 * 128);
        for (int i = t; i < 512; i += 256) ((float4*)sm)[i] = src[i];
        __syncthreads();
        int ntp = t >> 5, lane = t & 31;
        int tig = lane & 3, gid = lane >> 2;
        int c = tig * 2, n = ntp * 16 + gid;
        uint4 v;
        v.x = h2pack(sm[c * 128 + n],           sm[(c + 1) * 128 + n]);
        v.y = h2pack(sm[(c + 8) * 128 + n],     sm[(c + 9) * 128 + n]);
        v.z = h2pack(sm[c * 128 + n + 8],       sm[(c + 1) * 128 + n + 8]);
        v.w = h2pack(sm[(c + 8) * 128 + n + 8], sm[(c + 9) * 128 + n + 8]);
        g_bwf[blk * 256 + t] = v;
    } else if (blk < 1040) {
        int idx = (blk - 1024) * 256 + t;     // 4096 total, 16 blocks
        int ks = idx >> 7, ntp = (idx >> 5) & 3, lane = idx & 31;
        int tig = lane & 3, gid = lane >> 2;
        int c = ks * 16 + tig * 2, n = ntp * 16 + gid;
        uint4 v;
        v.x = h2pack(w2[n * 512 + c],           w2[n * 512 + c + 1]);
        v.y = h2pack(w2[n * 512 + c + 8],       w2[n * 512 + c + 9]);
        v.z = h2pack(w2[(n + 8) * 512 + c],     w2[(n + 8) * 512 + c + 1]);
        v.w = h2pack(w2[(n + 8) * 512 + c + 8], w2[(n + 8) * 512 + c + 9]);
        g_w2f[idx] = v;
    } else {
        if (t < 192) {
            int ks = t >> 6, ntp = (t >> 5) & 1, lane = t & 31;
            int tig = lane & 3, gid = lane >> 2;
            int c = ks * 16 + tig * 2, n = ntp * 16 + gid;
            uint4 v;
            v.x = h2pack(w1[n * 48 + c],           w1[n * 48 + c + 1]);
            v.y = h2pack(w1[n * 48 + c + 8],       w1[n * 48 + c + 9]);
            v.z = h2pack(w1[(n + 8) * 48 + c],     w1[(n + 8) * 48 + c + 1]);
            v.w = h2pack(w1[(n + 8) * 48 + c + 8], w1[(n + 8) * 48 + c + 9]);
            g_w1f[t] = v;
        }
    }
}

// ---------------------------------------------------------------------------
// Fused conv1+conv2 per image, fp16 m16n8k16. One CTA per image, 512 threads.
// Occupancy 2. conv2 B-fragments staged through the dead x_pad smem region in
// 4 chunks of 16KB (8 k-steps each): coalesced LDG once, conflict-free LDS
// in the mainloop (replaces 16x-redundant per-warp LDG.128 streams).
// ---------------------------------------------------------------------------
#define CB_ACT 0
#define CB_X   73984
#define CB_W1  100128
#define CB_P2  103200
#define CB_P1  105248
#define CB_BI1 105440
#define CB_BI2 105568
#define CB_TOT 105824

__global__ __launch_bounds__(512, 2) void fused_conv_kernel(
    const float* __restrict__ x_vis,
    const float* __restrict__ b1g, const float* __restrict__ b2g) {
    extern __shared__ char smc[];
    __half* act_s = (__half*)(smc + CB_ACT);
    __half* xs    = (__half*)(smc + CB_X);
    uint4*  w1f   = (uint4*)(smc + CB_W1);
    int*    p2t   = (int*)(smc + CB_P2);
    int*    p1t   = (int*)(smc + CB_P1);
    float*  bi1   = (float*)(smc + CB_BI1);
    float*  bi2   = (float*)(smc + CB_BI2);

    const int n = blockIdx.x, tid = threadIdx.x;
    const int lane = tid & 31, w = tid >> 5;
    const int tig = lane & 3, gid = lane >> 2;

    // zero act + x regions (6258 uint4)
    {
        uint4 z = make_uint4(0, 0, 0, 0);
        uint4* zp = (uint4*)smc;
        for (int t = tid; t < 6258; t += 512) zp[t] = z;
    }
    if (tid < 48)  p1t[tid] = (tid >> 4) * 4356 + ((tid >> 2) & 3) * 66 + (tid & 3);
    if (tid < 512) p2t[tid] = (tid >> 4) * 1156 + ((tid >> 2) & 3) * 34 + (tid & 3);
    if (tid < 192) w1f[tid] = g_w1f[tid];
    if (tid < 32) bi1[tid] = b1g[tid];
    if (tid < 64) bi2[tid] = b2g[tid];
    __syncthreads();

    // load x -> fp16 padded smem
    const float* xg = x_vis + (size_t)n * 12288;
    for (int t = tid; t < 12288; t += 512) {
        int ic = t >> 12, r = t & 4095, y = r >> 6, xx = r & 63;
        xs[ic * 4356 + (y + 1) * 66 + xx + 1] = __float2half_rn(xg[t]);
    }
    __syncthreads();

    // ---- conv1: M=1024, N=32, K=48 (3 k16-steps), two M-passes for regs ----
#pragma unroll
    for (int half = 0; half < 2; half++) {
        float acc1[2][4][4];
#pragma unroll
        for (int a = 0; a < 2; a++)
#pragma unroll
            for (int b = 0; b < 4; b++)
#pragma unroll
                for (int c = 0; c < 4; c++) acc1[a][b][c] = 0.f;
        int pbl[2], pbh[2];
#pragma unroll
        for (int mt = 0; mt < 2; mt++) {
            int pl = w * 64 + (half * 2 + mt) * 16 + gid, ph = pl + 8;
            pbl[mt] = ((pl >> 5) * 2) * 66 + (pl & 31) * 2;
            pbh[mt] = ((ph >> 5) * 2) * 66 + (ph & 31) * 2;
        }
#pragma unroll
        for (int ks = 0; ks < 3; ks++) {
            uint4 bv0 = w1f[(ks * 2 + 0) * 32 + lane];
            uint4 bv1 = w1f[(ks * 2 + 1) * 32 + lane];
            int c0 = ks * 16 + tig * 2;
            int o0 = p1t[c0], o1 = p1t[c0 + 8];
#pragma unroll
            for (int mt = 0; mt < 2; mt++) {
                unsigned a0 = *(const unsigned*)&xs[o0 + pbl[mt]];
                unsigned a1 = *(const unsigned*)&xs[o0 + pbh[mt]];
                unsigned a2 = *(const unsigned*)&xs[o1 + pbl[mt]];
                unsigned a3 = *(const unsigned*)&xs[o1 + pbh[mt]];
                MMA_F16(acc1[mt][0], a0, a1, a2, a3, bv0.x, bv0.y);
                MMA_F16(acc1[mt][1], a0, a1, a2, a3, bv0.z, bv0.w);
                MMA_F16(acc1[mt][2], a0, a1, a2, a3, bv1.x, bv1.y);
                MMA_F16(acc1[mt][3], a0, a1, a2, a3, bv1.z, bv1.w);
            }
        }
        // epilogue: relu+bias -> fp16 padded act smem [oc][y+1][x+1]
#pragma unroll
        for (int mt = 0; mt < 2; mt++) {
            int pl = w * 64 + (half * 2 + mt) * 16 + gid, ph = pl + 8;
            int yl = ((pl >> 5) + 1) * 34 + (pl & 31) + 1;
            int yh = ((ph >> 5) + 1) * 34 + (ph & 31) + 1;
#pragma unroll
            for (int nt = 0; nt < 4; nt++) {
                int oc = nt * 8 + 2 * tig;
                act_s[oc * 1156 + yl]       = __float2half_rn(fmaxf(acc1[mt][nt][0] + bi1[oc], 0.f));
                act_s[(oc + 1) * 1156 + yl] = __float2half_rn(fmaxf(acc1[mt][nt][1] + bi1[oc + 1], 0.f));
                act_s[oc * 1156 + yh]       = __float2half_rn(fmaxf(acc1[mt][nt][2] + bi1[oc], 0.f));
                act_s[(oc + 1) * 1156 + yh] = __float2half_rn(fmaxf(acc1[mt][nt][3] + bi1[oc + 1], 0.f));
            }
        }
    }
    __syncthreads();   // conv1 done: act_s valid, xs dead from here on

    // ---- conv2: M=256, N=64, K=512 (32 k16-steps), B staged via smem ----
    {
        uint4* wbuf = (uint4*)xs;   // reuse dead x_pad region (16KB chunks)
        float acc2[8][4];
#pragma unroll
        for (int a = 0; a < 8; a++)
#pragma unroll
            for (int c = 0; c < 4; c++) acc2[a][c] = 0.f;
        const int pl = w * 16 + gid, ph = pl + 8;
        const int pbl = ((pl >> 4) * 2) * 34 + (pl & 15) * 2;
        const int pbh = ((ph >> 4) * 2) * 34 + (ph & 15) * 2;

        for (int chunk = 0; chunk < 4; chunk++) {
            // stage 8 k-steps of B fragments: 1024 uint4, coalesced
            wbuf[tid] = g_w2f[chunk * 1024 + tid];
            wbuf[tid + 512] = g_w2f[chunk * 1024 + tid + 512];
            __syncthreads();
#pragma unroll 2
            for (int s8 = 0; s8 < 8; s8++) {
                int s = chunk * 8 + s8;
                int c0 = s * 16 + tig * 2;
                int o0 = p2t[c0], o1 = p2t[c0 + 8];
                const uint4* bp = &wbuf[s8 * 128 + lane];
                uint4 b0v = bp[0];
                uint4 b1v = bp[32];
                uint4 b2v = bp[64];
                uint4 b3v = bp[96];
                unsigned a0 = *(const unsigned*)&act_s[o0 + pbl];
                unsigned a1 = *(const unsigned*)&act_s[o0 + pbh];
                unsigned a2 = *(const unsigned*)&act_s[o1 + pbl];
                unsigned a3 = *(const unsigned*)&act_s[o1 + pbh];
                MMA_F16(acc2[0], a0, a1, a2, a3, b0v.x, b0v.y);
                MMA_F16(acc2[1], a0, a1, a2, a3, b0v.z, b0v.w);
                MMA_F16(acc2[2], a0, a1, a2, a3, b1v.x, b1v.y);
                MMA_F16(acc2[3], a0, a1, a2, a3, b1v.z, b1v.w);
                MMA_F16(acc2[4], a0, a1, a2, a3, b2v.x, b2v.y);
                MMA_F16(acc2[5], a0, a1, a2, a3, b2v.z, b2v.w);
                MMA_F16(acc2[6], a0, a1, a2, a3, b3v.x, b3v.y);
                MMA_F16(acc2[7], a0, a1, a2, a3, b3v.z, b3v.w);
            }
            __syncthreads();   // chunk consumed before overwrite
        }
        // epilogue -> g_feats fp16
        __half* fo = g_feats + (size_t)n * 16384;
#pragma unroll
        for (int nt = 0; nt < 8; nt++) {
            int oc = nt * 8 + 2 * tig;
            fo[oc * 256 + pl]       = __float2half_rn(fmaxf(acc2[nt][0] + bi2[oc], 0.f));
            fo[(oc + 1) * 256 + pl] = __float2half_rn(fmaxf(acc2[nt][1] + bi2[oc + 1], 0.f));
            fo[oc * 256 + ph]       = __float2half_rn(fmaxf(acc2[nt][2] + bi2[oc], 0.f));
            fo[(oc + 1) * 256 + ph] = __float2half_rn(fmaxf(acc2[nt][3] + bi2[oc + 1], 0.f));
        }
    }
}

// ---------------------------------------------------------------------------
// fp16 GEMM: g_prep[s] = feats(2048 x 1024-chunk) @ bbw-chunk (128 cols).
// Grid (16 M-tiles of 128, KSPLIT=16), 256 threads, reg-prefetch double buffer.
// ---------------------------------------------------------------------------
__global__ __launch_bounds__(256, 2) void gemm_pre_kernel() {
    __shared__ __half As[128 * 40];
    __shared__ uint4  Bs[512];
    const int tid = threadIdx.x, lane = tid & 31, w = tid >> 5;
    const int tig = lane & 3, gid = lane >> 2;
    const int m0 = blockIdx.x * 128;
    const int kb = blockIdx.y * 1024;
    const int arow = tid >> 1, acol = (tid & 1) * 16;

    float acc[16][4];
#pragma unroll
    for (int a = 0; a < 16; a++)
#pragma unroll
        for (int c = 0; c < 4; c++) acc[a][c] = 0.f;

    uint4 pa0, pa1, pb0, pb1;
#define G_LD(kt)                                                               \
    {                                                                          \
        const __half* ap = &g_feats[(size_t)(m0 + arow) * 16384 + kb + (kt) + acol]; \
        pa0 = *(const uint4*)ap;                                               \
        pa1 = *(const uint4*)(ap + 8);                                         \
        const uint4* bp = &g_bwf[((size_t)(kb + (kt)) >> 4) * 256 + tid];      \
        pb0 = bp[0];                                                           \
        pb1 = bp[256];                                                         \
    }
#define G_ST()                                                                 \
    {                                                                          \
        *(uint4*)&As[arow * 40 + acol] = pa0;                                  \
        *(uint4*)&As[arow * 40 + acol + 8] = pa1;                              \
        Bs[tid] = pb0;                                                         \
        Bs[tid + 256] = pb1;                                                   \
    }

    G_LD(0);
    G_ST();
    __syncthreads();

    for (int it = 0; it < 32; it++) {
        if (it < 31) G_LD((it + 1) * 32);
#pragma unroll
        for (int ks2 = 0; ks2 < 2; ks2++) {
            const __half* ap = &As[(w * 16 + gid) * 40 + ks2 * 16 + tig * 2];
            unsigned a0 = *(const unsigned*)ap;
            unsigned a1 = *(const unsigned*)(ap + 8 * 40);
            unsigned a2 = *(const unsigned*)(ap + 8);
            unsigned a3 = *(const unsigned*)(ap + 8 * 40 + 8);
#pragma unroll
            for (int ntp = 0; ntp < 8; ntp++) {
                uint4 bv = Bs[ks2 * 256 + ntp * 32 + lane];
                MMA_F16(acc[ntp * 2], a0, a1, a2, a3, bv.x, bv.y);
                MMA_F16(acc[ntp * 2 + 1], a0, a1, a2, a3, bv.z, bv.w);
            }
        }
        __syncthreads();
        if (it < 31) {
            G_ST();
            __syncthreads();
        }
    }

    float* op = g_prep + (size_t)blockIdx.y * (NT * 128);
    const int r0 = m0 + w * 16 + gid;
#pragma unroll
    for (int nt = 0; nt < 16; nt++) {
        *(float2*)&op[(size_t)r0 * 128 + nt * 8 + 2 * tig] = make_float2(acc[nt][0], acc[nt][1]);
        *(float2*)&op[(size_t)(r0 + 8) * 128 + nt * 8 + 2 * tig] = make_float2(acc[nt][2], acc[nt][3]);
    }
}

// ---------------------------------------------------------------------------
// CfC recurrent scan + logits. One CTA per batch, 512 threads.
// Register-resident weights stored as HALF2; math in fp32. Split-K partial
// sum folded into phase0's shfl reduction (4 lanes sum 4 of 16 slices each).
// ---------------------------------------------------------------------------
__global__ __launch_bounds__(512, 1) void recur_kernel(
                             const float* __restrict__ hx,
                             const float* __restrict__ bbw,
                             const float* __restrict__ bbb,
                             const float* __restrict__ f1w, const float* __restrict__ f1b,
                             const float* __restrict__ f2w, const float* __restrict__ f2b,
                             const float* __restrict__ taw, const float* __restrict__ tab,
                             const float* __restrict__ tbw, const float* __restrict__ tbb,
                             const float* __restrict__ ow,  const float* __restrict__ ob,
                             float* __restrict__ out, int out_size) {
    __shared__ float hs[64];
    __shared__ float bbs[128];
    __shared__ float heads[192];
    __shared__ float outs[64 * 68];
    __shared__ float outw[8 * 68];
    __shared__ float obs[8];
    const int b = blockIdx.x, tid = threadIdx.x;

    // phase0 ownership: output j0 (0..127), K-part p0 (0..3) of 16
    const int j0 = tid >> 2, p0 = tid & 3;
    __half2 w0h[8];
#pragma unroll
    for (int q = 0; q < 8; q++)
        w0h[q] = __floats2half2_rn(bbw[(size_t)(16384 + p0 * 16 + 2 * q) * 128 + j0],
                                   bbw[(size_t)(16384 + p0 * 16 + 2 * q + 1) * 128 + j0]);
    const float bias0 = bbb[j0];

    // phase1 ownership: output j1 (0..191), K-part p1 (0..1) of 64
    const int j1 = tid >> 1, p1 = tid & 1;
    const int m = (tid < 384) ? (j1 >> 6) : 0;
    const int i = j1 & 63;
    __half2 w1h[32];
    float bias1 = 0.f;
    if (tid < 384) {
        if (m == 2) {
#pragma unroll 8
            for (int q = 0; q < 32; q++) {
                int k = p1 * 64 + 2 * q;
                w1h[q] = __floats2half2_rn(taw[k * 64 + i] + tbw[k * 64 + i],
                                           taw[(k + 1) * 64 + i] + tbw[(k + 1) * 64 + i]);
            }
            bias1 = tab[i] + tbb[i];
        } else {
            const float* Wm = (m == 1) ? f2w : f1w;
#pragma unroll 8
            for (int q = 0; q < 32; q++) {
                int k = p1 * 64 + 2 * q;
                w1h[q] = __floats2half2_rn(Wm[k * 64 + i], Wm[(k + 1) * 64 + i]);
            }
            bias1 = (m == 1) ? f2b[i] : f1b[i];
        }
    }

    {
        int s = tid >> 3, o = tid & 7;
        outw[o * 68 + s] = ow[s * 8 + o];
    }
    if (tid < 8)  obs[tid] = ob[tid];
    if (tid < 64) hs[tid] = hx[b * 64 + tid];
    __syncthreads();

    const size_t base0 = (size_t)(b * TT) * 128 + j0;
    float nxt[4];
#pragma unroll
    for (int q = 0; q < 4; q++)
        nxt[q] = g_prep[(size_t)(p0 + 4 * q) * (NT * 128) + base0];

    for (int ts = 0; ts < TT; ts++) {
        float cur = (nxt[0] + nxt[1]) + (nxt[2] + nxt[3]);
        if (ts < TT - 1) {
#pragma unroll
            for (int q = 0; q < 4; q++)
                nxt[q] = g_prep[(size_t)(p0 + 4 * q) * (NT * 128) + base0 + (ts + 1) * 128];
        }
        // phase 0: bb = lecun_tanh(pre + h @ Wh), 4 lanes per output
        {
            float a0 = cur, a1 = 0.f;
            const float4* h4 = (const float4*)(hs + p0 * 16);
#pragma unroll
            for (int q = 0; q < 4; q++) {
                float4 hv = h4[q];
                float2 wa = __half22float2(w0h[2 * q]);
                float2 wb = __half22float2(w0h[2 * q + 1]);
                a0 += wa.x * hv.x + wa.y * hv.y;
                a1 += wb.x * hv.z + wb.y * hv.w;
            }
            float d = a0 + a1;
            d += __shfl_xor_sync(0xffffffffu, d, 1);
            d += __shfl_xor_sync(0xffffffffu, d, 2);
            if (p0 == 0)
                bbs[j0] = 1.7159f * fast_tanh(0.666f * (d + bias0));
        }
        __syncthreads();
        // phase 1: heads (ff1/ff2 tanh'd; merged gate linear), 2 lanes per output
        if (tid < 384) {
            float a0 = 0.f, a1 = 0.f, a2 = 0.f, a3 = 0.f;
            const float4* b4 = (const float4*)(bbs + p1 * 64);
#pragma unroll
            for (int q = 0; q < 16; q += 2) {
                float4 bv = b4[q];
                float2 wa = __half22float2(w1h[2 * q]);
                float2 wb = __half22float2(w1h[2 * q + 1]);
                a0 += wa.x * bv.x + wa.y * bv.y;
                a1 += wb.x * bv.z + wb.y * bv.w;
                float4 bv2 = b4[q + 1];
                float2 wc = __half22float2(w1h[2 * q + 2]);
                float2 wd = __half22float2(w1h[2 * q + 3]);
                a2 += wc.x * bv2.x + wc.y * bv2.y;
                a3 += wd.x * bv2.z + wd.y * bv2.w;
            }
            float d = (a0 + a1) + (a2 + a3);
            d += __shfl_xor_sync(0xffffffffu, d, 1);
            if (p1 == 0) {
                d += bias1;
                heads[j1] = (m < 2) ? fast_tanh(d) : d;
            }
        }
        __syncthreads();
        // phase 2: gated interpolation
        if (tid < 64) {
            float ti = fast_sig(heads[128 + tid]);
            float hn = heads[tid] * (1.f - ti) + ti * heads[64 + tid];
            hs[tid] = hn;
            outs[ts * 68 + tid] = hn;
        }
        __syncthreads();
    }

    // logits epilogue: 512 outputs, one per thread
    {
        int s = tid >> 3, o = tid & 7;
        float a0 = obs[o], a1 = 0.f;
        const float* r = &outs[s * 68];
        const float* wv = &outw[o * 68];
#pragma unroll
        for (int k = 0; k < 64; k += 2) {
            a0 += r[k] * wv[k];
            a1 += r[k + 1] * wv[k + 1];
        }
        out[(size_t)(b * TT + s) * 8 + o] = a0 + a1;
    }
    if (out_size >= 18432 && tid < 64) out[16384 + b * 64 + tid] = hs[tid];
}

// ---------------------------------------------------------------------------
extern "C" void kernel_launch(void* const* d_in, const int* in_sizes, int n_in,
                              void* d_out, int out_size) {
    const float* x_vis   = (const float*)d_in[0];
    const float* hx      = (const float*)d_in[1];
    const float* conv1_w = (const float*)d_in[2];
    const float* conv1_b = (const float*)d_in[3];
    const float* conv2_w = (const float*)d_in[4];
    const float* conv2_b = (const float*)d_in[5];
    const float* bb_w    = (const float*)d_in[6];
    const float* bb_b    = (const float*)d_in[7];
    const float* ff1_w   = (const float*)d_in[8];
    const float* ff1_b   = (const float*)d_in[9];
    const float* ff2_w   = (const float*)d_in[10];
    const float* ff2_b   = (const float*)d_in[11];
    const float* ta_w    = (const float*)d_in[12];
    const float* ta_b    = (const float*)d_in[13];
    const float* tb_w    = (const float*)d_in[14];
    const float* tb_b    = (const float*)d_in[15];
    const float* out_w   = (const float*)d_in[16];
    const float* out_b   = (const float*)d_in[17];
    float* out = (float*)d_out;

    const size_t smf = CB_TOT;                             // 105824 B (occ 2)

    cudaFuncSetAttribute(fused_conv_kernel, cudaFuncAttributeMaxDynamicSharedMemorySize, (int)smf);

    prep_kernel<<<1041, 256>>>(conv1_w, conv2_w, bb_w);
    fused_conv_kernel<<<NT, 512, smf>>>(x_vis, conv1_b, conv2_b);
    gemm_pre_kernel<<<dim3(16, KSPLIT), 256>>>();
    recur_kernel<<<BB, 512>>>(hx, bb_w, bb_b,
                              ff1_w, ff1_b, ff2_w, ff2_b,
                              ta_w, ta_b, tb_w, tb_b,
                              out_w, out_b, out, out_size);
}